// round 12
// baseline (speedup 1.0000x reference)
#include <cuda_runtime.h>

// filtfilt (butter(4,0.2)) over (8,64,48000) fp32 — fused smem kernel, v10.
// vs v9 (57.5us): amortize the fixed per-chunk warmup over longer chunks and
// shorten it. NSEG 8->6, L 26->34 (warmup FFMA/sample 11.8->7.2), W 40->32
// (0.7956^32 = 6.6e-4 bound; measured errors run ~2.5x below bound -> ~3e-4).
// SEGC=8008 (mod 4) + HALO=37 (=1 mod 4) keep all cp.async.bulk addresses and
// byte counts 16B-aligned. smem 35.1KB -> 6 blocks/SM (48 warps).

#define T_LEN  48000
#define PADL   15
#define TP     (T_LEN + 2 * PADL)   // 48030
#define ROWS   512
#define NSEG   6
#define SEGC   8008                 // mult of 4; 6*8008 = 48048 >= TP
#define NTHR   256
#define L      34                   // chunk per thread (stride conflict-free)
#define W      32                   // warmup depth (FIR truncation)
#define HALO   37                   // seam halo (>= W+4; == 1 mod 4)
#define BODY   (NTHR * L)           // 8704 >= SEGC + 2*HALO = 8082
#define SMEMN  (W + BODY + W)       // 8768 floats
#define SMEMF  (SMEMN * 4)          // 35072 B (16B multiple)
#define SMEMB  (SMEMF + 16)         // + mbarrier slot -> 6 blocks/SM

// Interior-segment constants (sg 1..4: full SEGC, no reflection)
#define EXTL_I (SEGC + 2 * HALO)    // 8082 valid body samples
#define LVEC   8080                 // bulk-loaded elements (mult of 4)
#define LBYTES (LVEC * 4)           // 32320 B
#define SVEC   (SEGC - 4)           // 8004 bulk-stored elements (mult of 4)
#define SBYTES (SVEC * 4)           // 32016 B

#define B0c 0.004824343357716228f
#define B1c 0.019297373430864913f
#define B2c 0.02894606014629737f
#define B3c 0.019297373430864913f
#define B4c 0.004824343357716228f
#define A1c (-2.369513007182038f)
#define A2c ( 2.3139884144006455f)
#define A3c (-1.0546654058785672f)
#define A4c ( 0.18737949236818502f)

// Impulse response h[k] of the IIR, computed at compile time.
struct HArr { float h[W]; };
__host__ __device__ constexpr HArr make_h() {
    HArr r{};
    double hd[W] = {};
    const double b[5] = {0.004824343357716228, 0.019297373430864913,
                         0.02894606014629737, 0.019297373430864913,
                         0.004824343357716228};
    const double a[4] = {-2.369513007182038, 2.3139884144006455,
                         -1.0546654058785672, 0.18737949236818502};
    for (int k = 0; k < W; ++k) {
        double v = (k < 5) ? b[k] : 0.0;
        for (int j = 0; j < 4; ++j)
            if (k - 1 - j >= 0) v -= a[j] * hd[k - 1 - j];
        hd[k] = v;
        r.h[k] = (float)v;
    }
    return r;
}

struct St { float w0, w1, w2, w3, s1, s2, s3, s4; };

// Truncated-FIR warmup over W samples in [base, base+W) (8B-aligned).
// REV=false: window precedes chunk (i = W-1-j back-distance).
// REV=true : window follows chunk (i = j back-distance).
template <bool REV>
__device__ __forceinline__ St fir_warmup(const float* base) {
    constexpr HArr HCk = make_h();
    const float2* p2 = reinterpret_cast<const float2*>(base);
    St st = {0.f, 0.f, 0.f, 0.f, 0.f, 0.f, 0.f, 0.f};
#pragma unroll
    for (int q = 0; q < W / 2; ++q) {
        float2 v = p2[q];
#pragma unroll
        for (int e = 0; e < 2; ++e) {
            const int j = 2 * q + e;
            const int i = REV ? j : (W - 1 - j);
            const float val = e ? v.y : v.x;
            st.s1 = fmaf(HCk.h[i], val, st.s1);
            if (i >= 1) st.s2 = fmaf(HCk.h[i - 1], val, st.s2);
            if (i >= 2) st.s3 = fmaf(HCk.h[i - 2], val, st.s3);
            if (i >= 3) st.s4 = fmaf(HCk.h[i - 3], val, st.s4);
            if (i == 0) st.w0 = val;
            if (i == 1) st.w1 = val;
            if (i == 2) st.w2 = val;
            if (i == 3) st.w3 = val;
        }
    }
    return st;
}

#define IIR_STEP(xn, yout)                                   \
    do {                                                     \
        float f_ = B0c * (xn);                               \
        f_ = fmaf(B1c, w0_, f_);                             \
        f_ = fmaf(B2c, w1_, f_);                             \
        f_ = fmaf(B3c, w2_, f_);                             \
        f_ = fmaf(B4c, w3_, f_);                             \
        f_ = fmaf(-A2c, s2_, f_);                            \
        f_ = fmaf(-A3c, s3_, f_);                            \
        f_ = fmaf(-A4c, s4_, f_);                            \
        (yout) = fmaf(-A1c, s1_, f_);                        \
        w3_ = w2_; w2_ = w1_; w1_ = w0_; w0_ = (xn);         \
        s4_ = s3_; s3_ = s2_; s2_ = s1_; s1_ = (yout);       \
    } while (0)

#define ST_UNPACK(st)                                         \
    float w0_ = st.w0, w1_ = st.w1, w2_ = st.w2, w3_ = st.w3, \
          s1_ = st.s1, s2_ = st.s2, s3_ = st.s3, s4_ = st.s4

__device__ __forceinline__ void mbar_wait0(unsigned mbar) {
    asm volatile(
        "{\n\t.reg .pred P%=;\n"
        "LW%=:\n\t"
        "mbarrier.try_wait.parity.acquire.cta.shared::cta.b64 P%=, [%0], 0;\n\t"
        "@!P%= bra LW%=;\n\t}"
        :: "r"(mbar) : "memory");
}

__global__ void __launch_bounds__(NTHR, 6)
fused_filtfilt(const float* __restrict__ x, float* __restrict__ out) {
    extern __shared__ float smem_raw[];
    float* xsp = smem_raw + W;               // body coord 0 (128B-aligned)
    const int tid = threadIdx.x;
    const int blk = blockIdx.x;
    const int r = blk / NSEG;
    const int sg = blk - r * NSEG;
    const float* __restrict__ xr = x + (size_t)r * T_LEN;
    float* __restrict__ outr = out + (size_t)r * T_LEN;

    const int core0 = sg * SEGC;
    const int core1 = min(core0 + SEGC, TP);
    const int e0 = max(0, core0 - HALO);
    const int ext_end = min(TP, core1 + HALO);
    const int ext_len = ext_end - e0;
    const bool interior = (sg != 0) && (sg != NSEG - 1);

    // ============ Load phase ============
    if (interior) {
        const unsigned mbar = (unsigned)__cvta_generic_to_shared(
            reinterpret_cast<char*>(smem_raw) + SMEMF);
        const float* src = xr + (e0 - PADL);          // 16B-aligned
        if (tid == 0)
            asm volatile("mbarrier.init.shared.b64 [%0], 1;" :: "r"(mbar) : "memory");
        // aprons + bulk tail (disjoint from the bulk region [W, W+LVEC))
        for (int i = tid; i < W; i += NTHR) smem_raw[i] = 0.f;
        if (tid < 2) xsp[LVEC + tid] = src[LVEC + tid];   // elements 8080,8081
        for (int i = W + EXTL_I + tid; i < SMEMN; i += NTHR) smem_raw[i] = 0.f;
        __syncthreads();                               // mbar init + zeros visible
        if (tid == 0) {
            const unsigned dst = (unsigned)__cvta_generic_to_shared(smem_raw + W);
            asm volatile(
                "mbarrier.arrive.expect_tx.shared.b64 _, [%0], %1;"
                :: "r"(mbar), "r"((unsigned)LBYTES) : "memory");
            asm volatile(
                "cp.async.bulk.shared::cta.global.mbarrier::complete_tx::bytes "
                "[%0], [%1], %2, [%3];"
                :: "r"(dst), "l"(src), "r"((unsigned)LBYTES), "r"(mbar) : "memory");
        }
        mbar_wait0(mbar);
    } else {
        for (int i = tid; i < SMEMN; i += NTHR) {
            int bi = i - W;
            float v = 0.f;
            if (bi >= 0 && bi < ext_len) {
                int j = e0 + bi - PADL;
                if (j < 0)           v = 2.f * xr[0]         - xr[-1 - j];
                else if (j >= T_LEN) v = 2.f * xr[T_LEN - 1] - xr[2 * T_LEN - 3 - j];
                else                 v = xr[j];
            }
            smem_raw[i] = v;
        }
        __syncthreads();
    }

    const int ps = tid * L;

    // ============ Forward pass (in place, float2) ============
    {
        St st = fir_warmup<false>(xsp + ps - W);
        ST_UNPACK(st);
        __syncthreads();                      // cross-chunk reads before writes
        float2* cp2 = reinterpret_cast<float2*>(xsp + ps);
        float y0, y1;
#pragma unroll
        for (int q = 0; q < L / 2; ++q) {
            float2 v = cp2[q];
            IIR_STEP(v.x, y0);
            IIR_STEP(v.y, y1);
            cp2[q] = make_float2(y0, y1);
        }
    }
    __syncthreads();

    // ---- Re-zero beyond valid extent (exact zero-init at padded row end) ----
    for (int i = ext_len + tid; i < BODY; i += NTHR) xsp[i] = 0.f;
    __syncthreads();

    // ============ Backward pass (in place, reversed, float2) ============
    {
        St st = fir_warmup<true>(xsp + ps + L);
        ST_UNPACK(st);
        __syncthreads();
        float2* cp2 = reinterpret_cast<float2*>(xsp + ps);
        float y0, y1;
#pragma unroll
        for (int q = L / 2 - 1; q >= 0; --q) {
            float2 v = cp2[q];
            IIR_STEP(v.y, y1);                // higher address first
            IIR_STEP(v.x, y0);
            cp2[q] = make_float2(y0, y1);
        }
    }
    __syncthreads();

    // ============ Store phase ============
    if (interior) {
        // scalar edges: p = core0+{0,1,2} head, core1-1 tail
        if (tid < 3) outr[core0 - PADL + tid] = xsp[HALO + tid];
        if (tid == 3) outr[core1 - 1 - PADL] = xsp[HALO + SEGC - 1];
        if (tid == 0) {
            const unsigned srcs = (unsigned)__cvta_generic_to_shared(
                xsp + HALO + 3);                       // 160B offset: aligned
            float* dst = outr + (core0 + 3 - PADL);    // 16B-aligned
            asm volatile("fence.proxy.async;" ::: "memory");
            asm volatile(
                "cp.async.bulk.global.shared::cta.bulk_group [%0], [%1], %2;"
                :: "l"(dst), "r"(srcs), "r"((unsigned)SBYTES) : "memory");
            asm volatile("cp.async.bulk.commit_group;" ::: "memory");
            asm volatile("cp.async.bulk.wait_group 0;" ::: "memory");
        }
    } else {
        const int wlo = max(core0, PADL);
        const int whi = min(core1, TP - PADL);
        for (int p = wlo + tid; p < whi; p += NTHR)
            outr[p - PADL] = xsp[p - e0];
    }
}

extern "C" void kernel_launch(void* const* d_in, const int* in_sizes, int n_in,
                              void* d_out, int out_size) {
    const float* x = (const float*)d_in[0];
    float* out = (float*)d_out;
    cudaFuncSetAttribute(fused_filtfilt,
                         cudaFuncAttributeMaxDynamicSharedMemorySize, SMEMB);
    fused_filtfilt<<<ROWS * NSEG, NTHR, SMEMB>>>(x, out);
}

// round 13
// speedup vs baseline: 1.1761x; 1.1761x over previous
#include <cuda_runtime.h>

// filtfilt (butter(4,0.2)) over (8,64,48000) fp32 — fused smem kernel, v11.
// = v9 geometry (NSEG=8, L=26, 8 blocks/SM, 32 regs — best latency hiding)
// + W 40->32 warmup (measured rel_err 2.3e-4, 4.4x margin)
// + re-zero folded into the forward pass (each thread zeroes its own chunk
//   beyond ext_len before the barrier) -> one less __syncthreads + loop.
// v10's NSEG=6 experiment showed occupancy dominates instruction count here.

#define T_LEN  48000
#define PADL   15
#define TP     (T_LEN + 2 * PADL)   // 48030
#define ROWS   512
#define NSEG   8
#define SEGC   6004                 // 8*6004 = 48032 >= TP
#define NTHR   256
#define L      26                   // chunk per thread (even, conflict-free v2)
#define W      32                   // warmup depth (FIR truncation)
#define HALO   45                   // seam halo; e0 = core0-45 == 3 (mod 4)
#define BODY   (NTHR * L)           // 6656 >= SEGC + 2*HALO = 6094
#define SMEMN  (W + BODY + W)       // 6720 floats
#define SMEMF  (SMEMN * 4)          // 26880 B (16B multiple)
#define SMEMB  (SMEMF + 16)         // + mbarrier slot -> 8 blocks/SM

// Interior-segment constants
#define EXTL_I (SEGC + 2 * HALO)    // 6094 valid body samples
#define LVEC   6092                 // bulk-loaded elements (mult of 4)
#define LBYTES (LVEC * 4)           // 24368 B
#define SVEC   (SEGC - 4)           // 6000 bulk-stored elements
#define SBYTES (SVEC * 4)           // 24000 B

#define B0c 0.004824343357716228f
#define B1c 0.019297373430864913f
#define B2c 0.02894606014629737f
#define B3c 0.019297373430864913f
#define B4c 0.004824343357716228f
#define A1c (-2.369513007182038f)
#define A2c ( 2.3139884144006455f)
#define A3c (-1.0546654058785672f)
#define A4c ( 0.18737949236818502f)

// Impulse response h[k] of the IIR, computed at compile time.
struct HArr { float h[W]; };
__host__ __device__ constexpr HArr make_h() {
    HArr r{};
    double hd[W] = {};
    const double b[5] = {0.004824343357716228, 0.019297373430864913,
                         0.02894606014629737, 0.019297373430864913,
                         0.004824343357716228};
    const double a[4] = {-2.369513007182038, 2.3139884144006455,
                         -1.0546654058785672, 0.18737949236818502};
    for (int k = 0; k < W; ++k) {
        double v = (k < 5) ? b[k] : 0.0;
        for (int j = 0; j < 4; ++j)
            if (k - 1 - j >= 0) v -= a[j] * hd[k - 1 - j];
        hd[k] = v;
        r.h[k] = (float)v;
    }
    return r;
}

struct St { float w0, w1, w2, w3, s1, s2, s3, s4; };

// Truncated-FIR warmup over W samples in [base, base+W) (8B-aligned).
// REV=false: window precedes chunk (i = W-1-j back-distance).
// REV=true : window follows chunk (i = j back-distance).
template <bool REV>
__device__ __forceinline__ St fir_warmup(const float* base) {
    constexpr HArr HCk = make_h();
    const float2* p2 = reinterpret_cast<const float2*>(base);
    St st = {0.f, 0.f, 0.f, 0.f, 0.f, 0.f, 0.f, 0.f};
#pragma unroll
    for (int q = 0; q < W / 2; ++q) {
        float2 v = p2[q];
#pragma unroll
        for (int e = 0; e < 2; ++e) {
            const int j = 2 * q + e;
            const int i = REV ? j : (W - 1 - j);
            const float val = e ? v.y : v.x;
            st.s1 = fmaf(HCk.h[i], val, st.s1);
            if (i >= 1) st.s2 = fmaf(HCk.h[i - 1], val, st.s2);
            if (i >= 2) st.s3 = fmaf(HCk.h[i - 2], val, st.s3);
            if (i >= 3) st.s4 = fmaf(HCk.h[i - 3], val, st.s4);
            if (i == 0) st.w0 = val;
            if (i == 1) st.w1 = val;
            if (i == 2) st.w2 = val;
            if (i == 3) st.w3 = val;
        }
    }
    return st;
}

#define IIR_STEP(xn, yout)                                   \
    do {                                                     \
        float f_ = B0c * (xn);                               \
        f_ = fmaf(B1c, w0_, f_);                             \
        f_ = fmaf(B2c, w1_, f_);                             \
        f_ = fmaf(B3c, w2_, f_);                             \
        f_ = fmaf(B4c, w3_, f_);                             \
        f_ = fmaf(-A2c, s2_, f_);                            \
        f_ = fmaf(-A3c, s3_, f_);                            \
        f_ = fmaf(-A4c, s4_, f_);                            \
        (yout) = fmaf(-A1c, s1_, f_);                        \
        w3_ = w2_; w2_ = w1_; w1_ = w0_; w0_ = (xn);         \
        s4_ = s3_; s3_ = s2_; s2_ = s1_; s1_ = (yout);       \
    } while (0)

#define ST_UNPACK(st)                                         \
    float w0_ = st.w0, w1_ = st.w1, w2_ = st.w2, w3_ = st.w3, \
          s1_ = st.s1, s2_ = st.s2, s3_ = st.s3, s4_ = st.s4

__device__ __forceinline__ void mbar_wait0(unsigned mbar) {
    asm volatile(
        "{\n\t.reg .pred P%=;\n"
        "LW%=:\n\t"
        "mbarrier.try_wait.parity.acquire.cta.shared::cta.b64 P%=, [%0], 0;\n\t"
        "@!P%= bra LW%=;\n\t}"
        :: "r"(mbar) : "memory");
}

__global__ void __launch_bounds__(NTHR, 8)
fused_filtfilt(const float* __restrict__ x, float* __restrict__ out) {
    extern __shared__ float smem_raw[];
    float* xsp = smem_raw + W;               // body coord 0 (128B-aligned)
    const int tid = threadIdx.x;
    const int blk = blockIdx.x;
    const int r = blk >> 3;
    const int sg = blk & 7;
    const float* __restrict__ xr = x + (size_t)r * T_LEN;
    float* __restrict__ outr = out + (size_t)r * T_LEN;

    const int core0 = sg * SEGC;
    const int core1 = min(core0 + SEGC, TP);
    const int e0 = max(0, core0 - HALO);
    const int ext_end = min(TP, core1 + HALO);
    const int ext_len = ext_end - e0;
    const bool interior = (sg != 0) && (sg != NSEG - 1);

    // ============ Load phase ============
    if (interior) {
        const unsigned mbar = (unsigned)__cvta_generic_to_shared(
            reinterpret_cast<char*>(smem_raw) + SMEMF);
        const float* src = xr + (e0 - PADL);          // 16B-aligned
        if (tid == 0)
            asm volatile("mbarrier.init.shared.b64 [%0], 1;" :: "r"(mbar) : "memory");
        // aprons + bulk tail (disjoint from the bulk region [W, W+LVEC))
        for (int i = tid; i < W; i += NTHR) smem_raw[i] = 0.f;
        if (tid < 2) xsp[LVEC + tid] = src[LVEC + tid];   // elements 6092,6093
        for (int i = W + EXTL_I + tid; i < SMEMN; i += NTHR) smem_raw[i] = 0.f;
        __syncthreads();                               // mbar init + zeros visible
        if (tid == 0) {
            const unsigned dst = (unsigned)__cvta_generic_to_shared(smem_raw + W);
            asm volatile(
                "mbarrier.arrive.expect_tx.shared.b64 _, [%0], %1;"
                :: "r"(mbar), "r"((unsigned)LBYTES) : "memory");
            asm volatile(
                "cp.async.bulk.shared::cta.global.mbarrier::complete_tx::bytes "
                "[%0], [%1], %2, [%3];"
                :: "r"(dst), "l"(src), "r"((unsigned)LBYTES), "r"(mbar) : "memory");
        }
        mbar_wait0(mbar);
    } else {
        for (int i = tid; i < SMEMN; i += NTHR) {
            int bi = i - W;
            float v = 0.f;
            if (bi >= 0 && bi < ext_len) {
                int j = e0 + bi - PADL;
                if (j < 0)           v = 2.f * xr[0]         - xr[-1 - j];
                else if (j >= T_LEN) v = 2.f * xr[T_LEN - 1] - xr[2 * T_LEN - 3 - j];
                else                 v = xr[j];
            }
            smem_raw[i] = v;
        }
        __syncthreads();
    }

    const int ps = tid * L;

    // ============ Forward pass (in place, float2) ============
    {
        St st = fir_warmup<false>(xsp + ps - W);
        ST_UNPACK(st);
        __syncthreads();                      // cross-chunk reads before writes
        float2* cp2 = reinterpret_cast<float2*>(xsp + ps);
        float y0, y1;
#pragma unroll
        for (int q = 0; q < L / 2; ++q) {
            float2 v = cp2[q];
            IIR_STEP(v.x, y0);
            IIR_STEP(v.y, y1);
            cp2[q] = make_float2(y0, y1);
        }
        // Self-zero this chunk's part beyond the valid extent: the backward
        // recursion must see exact zeros past the padded row end (reference
        // zero-init). Own-chunk writes only -> safe before the next barrier.
        if (ps + L > ext_len) {
            for (int t = max(ps, ext_len); t < ps + L; ++t) xsp[t] = 0.f;
        }
    }
    __syncthreads();

    // ============ Backward pass (in place, reversed, float2) ============
    {
        St st = fir_warmup<true>(xsp + ps + L);
        ST_UNPACK(st);
        __syncthreads();
        float2* cp2 = reinterpret_cast<float2*>(xsp + ps);
        float y0, y1;
#pragma unroll
        for (int q = L / 2 - 1; q >= 0; --q) {
            float2 v = cp2[q];
            IIR_STEP(v.y, y1);                // higher address first
            IIR_STEP(v.x, y0);
            cp2[q] = make_float2(y0, y1);
        }
    }
    __syncthreads();

    // ============ Store phase ============
    if (interior) {
        // scalar edges: p = core0+{0,1,2} head, core1-1 tail
        if (tid < 3) outr[core0 - PADL + tid] = xsp[HALO + tid];
        if (tid == 3) outr[core1 - 1 - PADL] = xsp[HALO + SEGC - 1];
        if (tid == 0) {
            const unsigned srcs = (unsigned)__cvta_generic_to_shared(
                xsp + HALO + 3);                       // 16B-aligned
            float* dst = outr + (core0 + 3 - PADL);    // 16B-aligned
            asm volatile("fence.proxy.async;" ::: "memory");
            asm volatile(
                "cp.async.bulk.global.shared::cta.bulk_group [%0], [%1], %2;"
                :: "l"(dst), "r"(srcs), "r"((unsigned)SBYTES) : "memory");
            asm volatile("cp.async.bulk.commit_group;" ::: "memory");
            asm volatile("cp.async.bulk.wait_group 0;" ::: "memory");
        }
    } else {
        const int wlo = max(core0, PADL);
        const int whi = min(core1, TP - PADL);
        for (int p = wlo + tid; p < whi; p += NTHR)
            outr[p - PADL] = xsp[p - e0];
    }
}

extern "C" void kernel_launch(void* const* d_in, const int* in_sizes, int n_in,
                              void* d_out, int out_size) {
    const float* x = (const float*)d_in[0];
    float* out = (float*)d_out;
    cudaFuncSetAttribute(fused_filtfilt,
                         cudaFuncAttributeMaxDynamicSharedMemorySize, SMEMB);
    fused_filtfilt<<<ROWS * NSEG, NTHR, SMEMB>>>(x, out);
}

// round 14
// speedup vs baseline: 1.6831x; 1.4310x over previous
#include <cuda_runtime.h>

// filtfilt (butter(4,0.2)) over (8,64,48000) fp32 — fused smem kernel, v12.
// vs v11 (55.8us): ALL 8 segments now use cp.async.bulk for load and store.
// Edge segments get an alignment-engineered body origin (sg0: e0=-13) so the
// real-signal slab is 16B-aligned on both sides; the <=15 odd-pad reflected
// samples are written by individual threads concurrently with the DMA.
// Zero regions before the padded row start reproduce the reference zero-IC
// exactly (zero state == zero-extended input). Bulk load is issued BEFORE
// the apron-zero loops (same-thread init->copy ordering) to overlap DMA.
// Compute core unchanged: NSEG=8, L=26 float2, W=32 FIR warmup, 32 regs.

#define T_LEN  48000
#define PADL   15
#define TP     (T_LEN + 2 * PADL)   // 48030
#define ROWS   512
#define NSEG   8
#define SEGC   6004                 // 8*6004 = 48032 >= TP
#define NTHR   256
#define L      26                   // chunk per thread (conflict-free float2)
#define W      32                   // warmup depth (FIR truncation)
#define HALO   45                   // interior halo; e0 == 3 (mod 4)
#define BODY   (NTHR * L)           // 6656
#define SMEMN  (W + BODY + W)       // 6720 floats
#define SMEMF  (SMEMN * 4)          // 26880 B
#define SMEMB  (SMEMF + 16)         // + mbarrier -> 8 blocks/SM

// Per-class constants
#define EXTI   6094                 // interior valid body samples
#define EXT0   6063                 // sg0  (e0=-13; p <= core1+HALO=6049)
#define EXT7   6047                 // sg7  (e0=41983; p <= TP-1)
#define LB_I   24368                // interior bulk load: 6092 elems
#define LB_E   24128                // edge bulk load: 6032 elems
#define SB_I   24000                // interior bulk store: 6000 elems
#define SB_0   23952                // sg0 bulk store: 5988 elems
#define SB_7   23936                // sg7 bulk store: 5984 elems

#define B0c 0.004824343357716228f
#define B1c 0.019297373430864913f
#define B2c 0.02894606014629737f
#define B3c 0.019297373430864913f
#define B4c 0.004824343357716228f
#define A1c (-2.369513007182038f)
#define A2c ( 2.3139884144006455f)
#define A3c (-1.0546654058785672f)
#define A4c ( 0.18737949236818502f)

// Impulse response h[k] of the IIR, computed at compile time.
struct HArr { float h[W]; };
__host__ __device__ constexpr HArr make_h() {
    HArr r{};
    double hd[W] = {};
    const double b[5] = {0.004824343357716228, 0.019297373430864913,
                         0.02894606014629737, 0.019297373430864913,
                         0.004824343357716228};
    const double a[4] = {-2.369513007182038, 2.3139884144006455,
                         -1.0546654058785672, 0.18737949236818502};
    for (int k = 0; k < W; ++k) {
        double v = (k < 5) ? b[k] : 0.0;
        for (int j = 0; j < 4; ++j)
            if (k - 1 - j >= 0) v -= a[j] * hd[k - 1 - j];
        hd[k] = v;
        r.h[k] = (float)v;
    }
    return r;
}

struct St { float w0, w1, w2, w3, s1, s2, s3, s4; };

// Truncated-FIR warmup over W samples in [base, base+W) (8B-aligned).
template <bool REV>
__device__ __forceinline__ St fir_warmup(const float* base) {
    constexpr HArr HCk = make_h();
    const float2* p2 = reinterpret_cast<const float2*>(base);
    St st = {0.f, 0.f, 0.f, 0.f, 0.f, 0.f, 0.f, 0.f};
#pragma unroll
    for (int q = 0; q < W / 2; ++q) {
        float2 v = p2[q];
#pragma unroll
        for (int e = 0; e < 2; ++e) {
            const int j = 2 * q + e;
            const int i = REV ? j : (W - 1 - j);
            const float val = e ? v.y : v.x;
            st.s1 = fmaf(HCk.h[i], val, st.s1);
            if (i >= 1) st.s2 = fmaf(HCk.h[i - 1], val, st.s2);
            if (i >= 2) st.s3 = fmaf(HCk.h[i - 2], val, st.s3);
            if (i >= 3) st.s4 = fmaf(HCk.h[i - 3], val, st.s4);
            if (i == 0) st.w0 = val;
            if (i == 1) st.w1 = val;
            if (i == 2) st.w2 = val;
            if (i == 3) st.w3 = val;
        }
    }
    return st;
}

#define IIR_STEP(xn, yout)                                   \
    do {                                                     \
        float f_ = B0c * (xn);                               \
        f_ = fmaf(B1c, w0_, f_);                             \
        f_ = fmaf(B2c, w1_, f_);                             \
        f_ = fmaf(B3c, w2_, f_);                             \
        f_ = fmaf(B4c, w3_, f_);                             \
        f_ = fmaf(-A2c, s2_, f_);                            \
        f_ = fmaf(-A3c, s3_, f_);                            \
        f_ = fmaf(-A4c, s4_, f_);                            \
        (yout) = fmaf(-A1c, s1_, f_);                        \
        w3_ = w2_; w2_ = w1_; w1_ = w0_; w0_ = (xn);         \
        s4_ = s3_; s3_ = s2_; s2_ = s1_; s1_ = (yout);       \
    } while (0)

#define ST_UNPACK(st)                                         \
    float w0_ = st.w0, w1_ = st.w1, w2_ = st.w2, w3_ = st.w3, \
          s1_ = st.s1, s2_ = st.s2, s3_ = st.s3, s4_ = st.s4

__device__ __forceinline__ void mbar_wait0(unsigned mbar) {
    asm volatile(
        "{\n\t.reg .pred P%=;\n"
        "LW%=:\n\t"
        "mbarrier.try_wait.parity.acquire.cta.shared::cta.b64 P%=, [%0], 0;\n\t"
        "@!P%= bra LW%=;\n\t}"
        :: "r"(mbar) : "memory");
}

__global__ void __launch_bounds__(NTHR, 8)
fused_filtfilt(const float* __restrict__ x, float* __restrict__ out) {
    extern __shared__ float smem_raw[];
    float* xsp = smem_raw + W;               // body coord 0 (128B-aligned)
    const int tid = threadIdx.x;
    const int blk = blockIdx.x;
    const int r = blk >> 3;
    const int sg = blk & 7;
    const float* __restrict__ xr = x + (size_t)r * T_LEN;
    float* __restrict__ outr = out + (size_t)r * T_LEN;

    const bool is0 = (sg == 0);
    const bool is7 = (sg == NSEG - 1);
    const int core0 = sg * SEGC;
    // body coord bi <-> padded coord p = e0 + bi
    const int e0 = is0 ? -13 : core0 - HALO;
    const int ext_len = is0 ? EXT0 : (is7 ? EXT7 : EXTI);

    // ============ Load phase (all classes: bulk + few scalars) ============
    {
        const unsigned mbar = (unsigned)__cvta_generic_to_shared(
            reinterpret_cast<char*>(smem_raw) + SMEMF);
        const float* src = is0 ? xr : (xr + (e0 - PADL));   // 16B-aligned
        const int dst_bi = is0 ? 28 : 0;                    // 16B-aligned dst
        const unsigned lbytes = (is0 || is7) ? LB_E : LB_I;
        if (tid == 0) {
            asm volatile("mbarrier.init.shared.b64 [%0], 1;" :: "r"(mbar) : "memory");
            asm volatile("mbarrier.arrive.expect_tx.shared.b64 _, [%0], %1;"
                         :: "r"(mbar), "r"(lbytes) : "memory");
            const unsigned dst = (unsigned)__cvta_generic_to_shared(xsp + dst_bi);
            asm volatile(
                "cp.async.bulk.shared::cta.global.mbarrier::complete_tx::bytes "
                "[%0], [%1], %2, [%3];"
                :: "r"(dst), "l"(src), "r"(lbytes), "r"(mbar) : "memory");
        }
        // zeros + reflected scalars, concurrent with DMA (disjoint regions)
        for (int i = tid; i < W; i += NTHR) smem_raw[i] = 0.f;   // leading apron
        for (int i = W + ext_len + tid; i < SMEMN; i += NTHR) smem_raw[i] = 0.f;
        if (is0) {
            if (tid < 13) xsp[tid] = 0.f;                        // p = -13..-1
            else if (tid < 28)                                   // p = 0..14 reflect
                xsp[tid] = 2.f * xr[0] - xr[27 - tid];           // x[14-(tid-13)]
            else if (tid < 31)                                   // bulk tail j 6032..6034
                xsp[6060 + (tid - 28)] = xr[6032 + (tid - 28)];
        } else if (is7) {
            if (tid < 15)                                        // p = 48015..48029
                xsp[6032 + tid] = 2.f * xr[T_LEN - 1] - xr[47997 - tid];
        } else {
            if (tid < 2) xsp[6092 + tid] = src[6092 + tid];      // bulk tail
        }
        __syncthreads();                 // mbar init + scalar writes visible
        mbar_wait0(mbar);
    }

    const int ps = tid * L;

    // ============ Forward pass (in place, float2) ============
    {
        St st = fir_warmup<false>(xsp + ps - W);
        ST_UNPACK(st);
        __syncthreads();                 // cross-chunk reads before writes
        float2* cp2 = reinterpret_cast<float2*>(xsp + ps);
        float y0, y1;
#pragma unroll
        for (int q = 0; q < L / 2; ++q) {
            float2 v = cp2[q];
            IIR_STEP(v.x, y0);
            IIR_STEP(v.y, y1);
            cp2[q] = make_float2(y0, y1);
        }
        // Self-zero beyond valid extent: backward recursion must see exact
        // zeros past the padded row end (reference zero-init semantics).
        if (ps + L > ext_len) {
            for (int t = max(ps, ext_len); t < ps + L; ++t) xsp[t] = 0.f;
        }
    }
    __syncthreads();

    // ============ Backward pass (in place, reversed, float2) ============
    {
        St st = fir_warmup<true>(xsp + ps + L);
        ST_UNPACK(st);
        __syncthreads();
        float2* cp2 = reinterpret_cast<float2*>(xsp + ps);
        float y0, y1;
#pragma unroll
        for (int q = L / 2 - 1; q >= 0; --q) {
            float2 v = cp2[q];
            IIR_STEP(v.y, y1);           // higher address first
            IIR_STEP(v.x, y0);
            cp2[q] = make_float2(y0, y1);
        }
    }
    __syncthreads();

    // ============ Store phase (all classes: scalars + bulk) ============
    if (is0) {
        // stored p in [15, 6004): out[0..5989); bi = p + 13
        if (tid == 1) outr[5988] = xsp[6016];                // p = 6003
        if (tid == 0) {
            const unsigned srcs = (unsigned)__cvta_generic_to_shared(xsp + 28);
            asm volatile("fence.proxy.async;" ::: "memory");
            asm volatile(
                "cp.async.bulk.global.shared::cta.bulk_group [%0], [%1], %2;"
                :: "l"(outr), "r"(srcs), "r"((unsigned)SB_0) : "memory");
            asm volatile("cp.async.bulk.commit_group;" ::: "memory");
            asm volatile("cp.async.bulk.wait_group 0;" ::: "memory");
        }
    } else {
        // head p = core0..core0+2 ; interior tail p = core1-1
        if (tid < 3) outr[core0 - PADL + tid] = xsp[HALO + tid];
        if (!is7 && tid == 3) outr[core0 + SEGC - 1 - PADL] = xsp[HALO + SEGC - 1];
        if (tid == 0) {
            const unsigned srcs = (unsigned)__cvta_generic_to_shared(xsp + HALO + 3);
            float* dst = outr + (core0 + 3 - PADL);
            const unsigned sbytes = is7 ? SB_7 : SB_I;
            asm volatile("fence.proxy.async;" ::: "memory");
            asm volatile(
                "cp.async.bulk.global.shared::cta.bulk_group [%0], [%1], %2;"
                :: "l"(dst), "r"(srcs), "r"(sbytes) : "memory");
            asm volatile("cp.async.bulk.commit_group;" ::: "memory");
            asm volatile("cp.async.bulk.wait_group 0;" ::: "memory");
        }
    }
}

extern "C" void kernel_launch(void* const* d_in, const int* in_sizes, int n_in,
                              void* d_out, int out_size) {
    const float* x = (const float*)d_in[0];
    float* out = (float*)d_out;
    cudaFuncSetAttribute(fused_filtfilt,
                         cudaFuncAttributeMaxDynamicSharedMemorySize, SMEMB);
    fused_filtfilt<<<ROWS * NSEG, NTHR, SMEMB>>>(x, out);
}